// round 9
// baseline (speedup 1.0000x reference)
#include <cuda_runtime.h>

#define T_    16384
#define TILE  256              // elements per warp-tile (8 per lane)
#define SPAN  2048             // output elements per warp
#define SPANS (T_ / SPAN)      // 8 warps per row
#define MT    (SPAN / TILE)    // 8 main tiles per warp
#define WPC   4
#define FULL  0xffffffffu

struct Ser { float b, w1, w2, w3, w4, w5, w6, pw; };

__device__ __forceinline__ Ser make_ser(float b, int lane) {
    Ser s; s.b = b;
    float b2 = b * b, b4 = b2 * b2;
    s.w1 = b4 * b4;          // b^8
    s.w2 = s.w1 * s.w1;      // b^16
    s.w3 = s.w2 * s.w2;      // b^32
    s.w4 = s.w3 * s.w3;      // b^64
    s.w5 = s.w4 * s.w4;      // b^128
    s.w6 = s.w5 * s.w5;      // b^256 (whole-tile weight for the carry)
    float pw = 1.f, p = s.w1;
#pragma unroll
    for (int k = 0; k < 5; ++k) { if (lane & (1 << k)) pw *= p; p *= p; }
    s.pw = pw;               // b^(8*lane)
    return s;
}

// Inclusive scan of F_t = b*F_{t-1} + x_t over a 256-elt tile (8 per lane).
// S is the state BEFORE the tile's first element; updated off the reconstruct
// path (S' = b^256*S + tot).
__device__ __forceinline__ void scan8(const Ser s, const float xv[8],
                                      float y[8], float& S, int lane)
{
    float Bv = xv[0];
#pragma unroll
    for (int i = 1; i < 8; ++i) Bv = fmaf(s.b, Bv, xv[i]);
    float t;
    t = __shfl_up_sync(FULL, Bv, 1);  if (lane >= 1)  Bv = fmaf(s.w1, t, Bv);
    t = __shfl_up_sync(FULL, Bv, 2);  if (lane >= 2)  Bv = fmaf(s.w2, t, Bv);
    t = __shfl_up_sync(FULL, Bv, 4);  if (lane >= 4)  Bv = fmaf(s.w3, t, Bv);
    t = __shfl_up_sync(FULL, Bv, 8);  if (lane >= 8)  Bv = fmaf(s.w4, t, Bv);
    t = __shfl_up_sync(FULL, Bv, 16); if (lane >= 16) Bv = fmaf(s.w5, t, Bv);
    float sb  = __shfl_up_sync(FULL, Bv, 1);
    float tot = __shfl_sync(FULL, Bv, 31);
    sb = (lane == 0) ? 0.f : sb;
    float e = fmaf(s.pw, S, sb);
#pragma unroll
    for (int i = 0; i < 8; ++i) { e = fmaf(s.b, e, xv[i]); y[i] = e; }
    S = fmaf(s.w6, S, tot);
}

// Carry-only variant for the warmup tile: no reconstruct.
__device__ __forceinline__ void scanc(const Ser s, const float xv[8],
                                      float& S, int lane)
{
    float Bv = xv[0];
#pragma unroll
    for (int i = 1; i < 8; ++i) Bv = fmaf(s.b, Bv, xv[i]);
    float t;
    t = __shfl_up_sync(FULL, Bv, 1);  if (lane >= 1)  Bv = fmaf(s.w1, t, Bv);
    t = __shfl_up_sync(FULL, Bv, 2);  if (lane >= 2)  Bv = fmaf(s.w2, t, Bv);
    t = __shfl_up_sync(FULL, Bv, 4);  if (lane >= 4)  Bv = fmaf(s.w3, t, Bv);
    t = __shfl_up_sync(FULL, Bv, 8);  if (lane >= 8)  Bv = fmaf(s.w4, t, Bv);
    t = __shfl_up_sync(FULL, Bv, 16); if (lane >= 16) Bv = fmaf(s.w5, t, Bv);
    float tot = __shfl_sync(FULL, Bv, 31);
    S = fmaf(s.w6, S, tot);
}

__device__ __forceinline__ void load8(float v[8], const float* __restrict__ p) {
    const float4 a = *(const float4*)p;
    const float4 b = *(const float4*)(p + 4);
    v[0]=a.x; v[1]=a.y; v[2]=a.z; v[3]=a.w;
    v[4]=b.x; v[5]=b.y; v[6]=b.z; v[7]=b.w;
}

__global__ __launch_bounds__(32 * WPC)
void macd_scan(const float* __restrict__ x,
               const int* __restrict__ ps_, const int* __restrict__ pl_,
               const int* __restrict__ pg_,
               float* __restrict__ out, int B)
{
    const int lane = threadIdx.x & 31;
    const int w    = blockIdx.x * WPC + (threadIdx.x >> 5);
    const int row  = w / SPANS;
    const int span = w - row * SPANS;
    if (row >= B) return;

    const float a_s = 2.f / (float)(ps_[0] + 1), b_s = 1.f - a_s;
    const float a_l = 2.f / (float)(pl_[0] + 1), b_l = 1.f - a_l;
    const float a_g = 2.f / (float)(pg_[0] + 1), b_g = 1.f - a_g;
    const Ser ss = make_ser(b_s, lane);
    const Ser sl = make_ser(b_l, lane);
    const Ser sg = make_ser(b_g, lane);

    // Partial-fraction coefficients: sig = Ks*Fs + Kl*Fl + Kg*Fg.
    const float r_s = __fdividef(1.f, b_g - b_s);
    const float r_l = __fdividef(1.f, b_g - b_l);
    const float K_s = -a_g * a_s * b_s * r_s;     // = ag*as*bs/(bs-bg)
    const float K_l =  a_g * a_l * b_l * r_l;     // = ag*al*bl/(bg-bl)
    const float K_g =  a_g * b_g * (a_s * r_s - a_l * r_l);
    // Carry inits (make y_0 = x_0 exact; sig transient folds into S_g).
    const float inv_as = __fdividef(1.f, a_s);
    const float inv_al = __fdividef(1.f, a_l);
    const float sg_num = b_s * r_s - b_l * r_l;
    const float sg_den = b_g * (a_s * r_s - a_l * r_l);
    const float sg_c   = __fdividef(sg_num, sg_den);

    const size_t rbase = (size_t)row * T_;
    const int    off0  = span * SPAN;
    const size_t N     = (size_t)B * T_;
    const float* __restrict__ xp = x + rbase;
    float* __restrict__ om = out;
    float* __restrict__ og = out + N;
    float* __restrict__ oh = out + 2 * N;

    float Ss, Sl, Sg;

    if (span == 0) {
        const float x0 = __ldg(xp);
        Ss = x0 * inv_as; Sl = x0 * inv_al; Sg = x0 * sg_c;
    } else {
        // Self-start warmup over one tile [off0-256, off0): carries only.
        float wv[8];
        load8(wv, xp + (off0 - TILE) + lane * 8);
        const float x0 = __shfl_sync(FULL, wv[0], 0);
        Ss = x0 * inv_as; Sl = x0 * inv_al; Sg = x0 * sg_c;
        scanc(ss, wv, Ss, lane);
        scanc(sl, wv, Sl, lane);
        scanc(sg, wv, Sg, lane);
    }

#pragma unroll 2
    for (int t = 0; t < MT; ++t) {
        const size_t base = rbase + (size_t)off0 + t * TILE + lane * 8;
        float xv[8];
        load8(xv, x + base);
        float ys[8], yl[8], yg[8];
        scan8(ss, xv, ys, Ss, lane);   // three INDEPENDENT scans:
        scan8(sl, xv, yl, Sl, lane);   // shfl chains interleave (3x ILP)
        scan8(sg, xv, yg, Sg, lane);

        float m[8], g[8];
#pragma unroll
        for (int i = 0; i < 8; ++i) {
            m[i] = fmaf(a_s, ys[i], -a_l * yl[i]);
            g[i] = fmaf(K_s, ys[i], fmaf(K_l, yl[i], K_g * yg[i]));
        }

        *(float4*)(om + base)     = make_float4(m[0], m[1], m[2], m[3]);
        *(float4*)(om + base + 4) = make_float4(m[4], m[5], m[6], m[7]);
        *(float4*)(og + base)     = make_float4(g[0], g[1], g[2], g[3]);
        *(float4*)(og + base + 4) = make_float4(g[4], g[5], g[6], g[7]);
        *(float4*)(oh + base)     = make_float4(m[0] - g[0], m[1] - g[1],
                                                m[2] - g[2], m[3] - g[3]);
        *(float4*)(oh + base + 4) = make_float4(m[4] - g[4], m[5] - g[5],
                                                m[6] - g[6], m[7] - g[7]);
    }
}

extern "C" void kernel_launch(void* const* d_in, const int* in_sizes, int n_in,
                              void* d_out, int out_size)
{
    const float* x  = (const float*)d_in[0];
    const int*   ps = (const int*)d_in[1];
    const int*   pl = (const int*)d_in[2];
    const int*   pg = (const int*)d_in[3];

    const int B = in_sizes[0] / T_;
    float* out = (float*)d_out;

    const int total_warps = B * SPANS;
    const int blocks = (total_warps + WPC - 1) / WPC;

    macd_scan<<<blocks, 32 * WPC>>>(x, ps, pl, pg, out, B);
}

// round 10
// speedup vs baseline: 1.1655x; 1.1655x over previous
#include <cuda_runtime.h>

#define T_    16384
#define TILE  256              // elements per warp-tile (8 per lane)
#define SPAN  2048             // output elements per warp
#define SPANS (T_ / SPAN)      // 8 warps per row
#define MT    (SPAN / TILE)    // 8 main tiles per warp
#define WPC   4
#define FULL  0xffffffffu

struct Ser { float b, w1, w2, w3, w4, w5, w6, pw; };

__device__ __forceinline__ Ser make_ser(float b, int lane) {
    Ser s; s.b = b;
    float b2 = b * b, b4 = b2 * b2;
    s.w1 = b4 * b4;          // b^8
    s.w2 = s.w1 * s.w1;      // b^16
    s.w3 = s.w2 * s.w2;      // b^32
    s.w4 = s.w3 * s.w3;      // b^64
    s.w5 = s.w4 * s.w4;      // b^128
    s.w6 = s.w5 * s.w5;      // b^256 (whole-tile carry weight)
    float pw = 1.f, p = s.w1;
#pragma unroll
    for (int k = 0; k < 5; ++k) { if (lane & (1 << k)) pw *= p; p *= p; }
    s.pw = pw;               // b^(8*lane)
    return s;
}

// Compose + Kogge-Stone phase only. Returns sb = zero-history prefix entering
// this lane, tot = whole-tile inclusive value (lane31). NO reconstruct here —
// three calls for the three series are fully independent, so their 5-deep
// shfl chains interleave.
__device__ __forceinline__ void ksphase(const Ser s, const float xv[8],
                                        float& sb, float& tot, int lane)
{
    float Bv = xv[0];
#pragma unroll
    for (int i = 1; i < 8; ++i) Bv = fmaf(s.b, Bv, xv[i]);
    float t;
    t = __shfl_up_sync(FULL, Bv, 1);  if (lane >= 1)  Bv = fmaf(s.w1, t, Bv);
    t = __shfl_up_sync(FULL, Bv, 2);  if (lane >= 2)  Bv = fmaf(s.w2, t, Bv);
    t = __shfl_up_sync(FULL, Bv, 4);  if (lane >= 4)  Bv = fmaf(s.w3, t, Bv);
    t = __shfl_up_sync(FULL, Bv, 8);  if (lane >= 8)  Bv = fmaf(s.w4, t, Bv);
    t = __shfl_up_sync(FULL, Bv, 16); if (lane >= 16) Bv = fmaf(s.w5, t, Bv);
    sb  = __shfl_up_sync(FULL, Bv, 1);
    tot = __shfl_sync(FULL, Bv, 31);
    if (lane == 0) sb = 0.f;
}

__device__ __forceinline__ void load8(float v[8], const float* __restrict__ p) {
    const float4 a = *(const float4*)p;
    const float4 b = *(const float4*)(p + 4);
    v[0]=a.x; v[1]=a.y; v[2]=a.z; v[3]=a.w;
    v[4]=b.x; v[5]=b.y; v[6]=b.z; v[7]=b.w;
}

__global__ __launch_bounds__(32 * WPC)
void macd_scan(const float* __restrict__ x,
               const int* __restrict__ ps_, const int* __restrict__ pl_,
               const int* __restrict__ pg_,
               float* __restrict__ out, int B)
{
    const int lane = threadIdx.x & 31;
    const int w    = blockIdx.x * WPC + (threadIdx.x >> 5);
    const int row  = w / SPANS;
    const int span = w - row * SPANS;
    if (row >= B) return;

    const float a_s = 2.f / (float)(ps_[0] + 1), b_s = 1.f - a_s;
    const float a_l = 2.f / (float)(pl_[0] + 1), b_l = 1.f - a_l;
    const float a_g = 2.f / (float)(pg_[0] + 1), b_g = 1.f - a_g;
    const Ser ss = make_ser(b_s, lane);
    const Ser sl = make_ser(b_l, lane);
    const Ser sg = make_ser(b_g, lane);

    // Partial fractions: sig = Ks*Fs + Kl*Fl + Kg*Fg (F = unnormalized EMAs
    // driven by raw x).  macd = a_s*Fs - a_l*Fl.
    const float r_s = __fdividef(1.f, b_g - b_s);
    const float r_l = __fdividef(1.f, b_g - b_l);
    const float K_s = -a_g * a_s * b_s * r_s;
    const float K_l =  a_g * a_l * b_l * r_l;
    const float K_g =  a_g * b_g * (a_s * r_s - a_l * r_l);
    // Carry inits (exact y_0 = x_0; signal transient folds into S_g).
    const float inv_as = __fdividef(1.f, a_s);
    const float inv_al = __fdividef(1.f, a_l);
    const float sg_c   = __fdividef(b_s * r_s - b_l * r_l,
                                    b_g * (a_s * r_s - a_l * r_l));

    const size_t rbase = (size_t)row * T_;
    const int    off0  = span * SPAN;
    const size_t N     = (size_t)B * T_;
    const float* __restrict__ xp = x + rbase;
    float* __restrict__ om = out;
    float* __restrict__ og = out + N;
    float* __restrict__ oh = out + 2 * N;

    float Ss, Sl, Sg;

    if (span == 0) {
        const float x0 = __ldg(xp);
        Ss = x0 * inv_as; Sl = x0 * inv_al; Sg = x0 * sg_c;
    } else {
        // Self-start warmup, one tile [off0-256, off0): carries only.
        float wv[8];
        load8(wv, xp + (off0 - TILE) + lane * 8);
        const float x0 = __shfl_sync(FULL, wv[0], 0);
        Ss = x0 * inv_as; Sl = x0 * inv_al; Sg = x0 * sg_c;
        float sb0, t0, sb1, t1, sb2, t2;
        ksphase(ss, wv, sb0, t0, lane);
        ksphase(sl, wv, sb1, t1, lane);
        ksphase(sg, wv, sb2, t2, lane);
        Ss = fmaf(ss.w6, Ss, t0);
        Sl = fmaf(sl.w6, Sl, t1);
        Sg = fmaf(sg.w6, Sg, t2);
    }

#pragma unroll 2
    for (int t = 0; t < MT; ++t) {
        const size_t base = rbase + (size_t)off0 + t * TILE + lane * 8;
        float xv[8];
        load8(xv, x + base);

        // Three independent KS phases (shfl chains interleave 3-wide).
        float sbs, tots, sbl, totl, sbg, totg;
        ksphase(ss, xv, sbs, tots, lane);
        ksphase(sl, xv, sbl, totl, lane);
        ksphase(sg, xv, sbg, totg, lane);

        // Lane-entry states; carries updated immediately (off critical path).
        float es = fmaf(ss.pw, Ss, sbs);
        float el = fmaf(sl.pw, Sl, sbl);
        float eg = fmaf(sg.pw, Sg, sbg);
        Ss = fmaf(ss.w6, Ss, tots);
        Sl = fmaf(sl.w6, Sl, totl);
        Sg = fmaf(sg.w6, Sg, totg);

        // Fused reconstruct + combine + store: no y arrays ever materialized.
#pragma unroll
        for (int hh = 0; hh < 2; ++hh) {
            float4 M, G, H;
            float* Mp = &M.x; float* Gp = &G.x; float* Hp = &H.x;
#pragma unroll
            for (int j = 0; j < 4; ++j) {
                const float xvj = xv[hh * 4 + j];
                es = fmaf(b_s, es, xvj);
                el = fmaf(b_l, el, xvj);
                eg = fmaf(b_g, eg, xvj);
                const float m = fmaf(a_s, es, -(a_l * el));
                const float g = fmaf(K_s, es, fmaf(K_l, el, K_g * eg));
                Mp[j] = m; Gp[j] = g; Hp[j] = m - g;
            }
            *(float4*)(om + base + hh * 4) = M;
            *(float4*)(og + base + hh * 4) = G;
            *(float4*)(oh + base + hh * 4) = H;
        }
    }
}

extern "C" void kernel_launch(void* const* d_in, const int* in_sizes, int n_in,
                              void* d_out, int out_size)
{
    const float* x  = (const float*)d_in[0];
    const int*   ps = (const int*)d_in[1];
    const int*   pl = (const int*)d_in[2];
    const int*   pg = (const int*)d_in[3];

    const int B = in_sizes[0] / T_;
    float* out = (float*)d_out;

    const int total_warps = B * SPANS;
    const int blocks = (total_warps + WPC - 1) / WPC;

    macd_scan<<<blocks, 32 * WPC>>>(x, ps, pl, pg, out, B);
}